// round 16
// baseline (speedup 1.0000x reference)
#include <cuda_runtime.h>
#include <cuda_fp16.h>
#include <math.h>
#include <math_constants.h>

// Problem constants
#define Bz   2
#define Nn   4096
#define DIMM 1024
#define Hh   16
#define Dd   64
#define Mm   266
#define BHh  (Bz*Hh)        // 32
#define ROWS (Bz*Nn)        // 8192
#define LDP  288            // padded feature row length

#define NORMALIZER 0.35355339059327373f   // 64^-0.25
#define RATIO      0.061313933948496576f  // 266^-0.5
#define EPSV       1e-4f
#define LOG2E      1.4426950408889634f

#define STAGES  5
#define PITCHH  40
#define HSTGB   (128*PITCHH*2)                     // 10240 B per operand stage
#define HBOFFB  (STAGES*HSTGB)                     // 51200 B
#define CORE_SMEM (STAGES*HSTGB*2)                 // 102400 B

// ---------------- scratch -------------------------------------------------------
__device__ __half g_xh[ROWS*DIMM];
__device__ __half g_wh[4*(size_t)DIMM*DIMM];
__device__ __half g_projh[384*Dd];
__device__ __half g_qh[ROWS*DIMM];
__device__ __half g_kh[ROWS*DIMM];
__device__ __half g_vh[ROWS*DIMM];
__device__ __half g_attnh[ROWS*DIMM];
__device__ __half g_qpd[(size_t)BHh*Nn*LDP + 128]; // raw q dash -> features (in-place)
__device__ __half g_kpd[(size_t)BHh*Nn*LDP + 128]; // raw k dash -> features (in-place)
__device__ float  g_kmax[BHh];
__device__ float  g_kcum[BHh*LDP];
__device__ float  g_ctxT[(size_t)BHh*128*LDP];     // fp32 atomics target [e][m]
__device__ __half g_ctxTh[(size_t)BHh*128*LDP];    // row 64 = kcum; 65..127 stay 0

// ---------------- helpers -------------------------------------------------------
__device__ __forceinline__ unsigned smem_u32(const void* p) {
    unsigned a;
    asm("{ .reg .u64 t; cvta.to.shared.u64 t, %1; cvt.u32.u64 %0, t; }" : "=r"(a) : "l"(p));
    return a;
}
__device__ __forceinline__ float fexp(float x) {
    float y;
    asm("ex2.approx.f32 %0, %1;" : "=f"(y) : "f"(x * LOG2E));
    return y;
}
__device__ __forceinline__ void cp16(unsigned dst, const void* src) {
    asm volatile("cp.async.ca.shared.global [%0], [%1], 16;" :: "r"(dst), "l"(src));
}
__device__ __forceinline__ void ldsm4(unsigned& r0, unsigned& r1, unsigned& r2, unsigned& r3,
                                      unsigned addr) {
    asm volatile("ldmatrix.sync.aligned.m8n8.x4.shared.b16 {%0,%1,%2,%3}, [%4];"
        : "=r"(r0), "=r"(r1), "=r"(r2), "=r"(r3) : "r"(addr));
}
__device__ __forceinline__ void ldsm4t(unsigned& r0, unsigned& r1, unsigned& r2, unsigned& r3,
                                       unsigned addr) {
    asm volatile("ldmatrix.sync.aligned.m8n8.x4.trans.shared.b16 {%0,%1,%2,%3}, [%4];"
        : "=r"(r0), "=r"(r1), "=r"(r2), "=r"(r3) : "r"(addr));
}
__device__ __forceinline__ void mma_f16(float c[4],
                                        unsigned a0, unsigned a1, unsigned a2, unsigned a3,
                                        unsigned b0, unsigned b1) {
    asm volatile(
        "mma.sync.aligned.m16n8k16.row.col.f32.f16.f16.f32 "
        "{%0,%1,%2,%3}, {%4,%5,%6,%7}, {%8,%9}, {%0,%1,%2,%3};"
        : "+f"(c[0]), "+f"(c[1]), "+f"(c[2]), "+f"(c[3])
        : "r"(a0), "r"(a1), "r"(a2), "r"(a3), "r"(b0), "r"(b1));
}
__device__ __forceinline__ void atomicMaxFloat(float* addr, float val) {
    int* a = (int*)addr;
    int old = *a;
    while (__int_as_float(old) < val) {
        int assumed = old;
        old = atomicCAS(a, assumed, __float_as_int(val));
        if (old == assumed) break;
    }
}

// ---------------- prep / conversion passes -----------------------------------------
__global__ void prep_small(const float* __restrict__ proj) {
    size_t t = (size_t)blockIdx.x * blockDim.x + threadIdx.x;
    if (t < BHh) g_kmax[t] = -CUDART_INF_F;
    if (t < BHh * LDP) g_kcum[t] = 0.f;
    if (t < 384 * Dd) {
        int m = (int)(t >> 6);
        g_projh[t] = (m < Mm) ? __float2half_rn(proj[t] * NORMALIZER) : __half(0.f);
    }
    if (t < (size_t)BHh * Dd * LDP) {
        size_t bh = t / (Dd * LDP);
        size_t rem = t - bh * (Dd * LDP);
        g_ctxT[bh * 128 * LDP + rem] = 0.f;
    }
}
__global__ void round_xh(const float* __restrict__ in) {
    int i = blockIdx.x * blockDim.x + threadIdx.x;
    float4 v = ((const float4*)in)[i];
    ((__half2*)g_xh)[2*i]   = __floats2half2_rn(v.x, v.y);
    ((__half2*)g_xh)[2*i+1] = __floats2half2_rn(v.z, v.w);
}
__global__ void round_wh(const float* __restrict__ w0, const float* __restrict__ w1,
                         const float* __restrict__ w2, const float* __restrict__ w3) {
    int z = blockIdx.y;
    const float* w = (z == 0) ? w0 : (z == 1) ? w1 : (z == 2) ? w2 : w3;
    int i = blockIdx.x * blockDim.x + threadIdx.x;
    float4 v = ((const float4*)w)[i];
    __half2* o = (__half2*)(g_wh + (size_t)z * DIMM * DIMM);
    o[2*i]   = __floats2half2_rn(v.x, v.y);
    o[2*i+1] = __floats2half2_rn(v.z, v.w);
}
__global__ void fix_kernel() {
    size_t t = (size_t)blockIdx.x * 256 + threadIdx.x;
    const size_t per_bh = (size_t)65 * LDP;
    if (t >= (size_t)BHh * per_bh) return;
    size_t bh = t / per_bh;
    size_t rem = t - bh * per_bh;
    int row = (int)(rem / LDP), m = (int)(rem - (size_t)row * LDP);
    float v = (row < 64) ? g_ctxT[(bh * 128 + row) * LDP + m] : g_kcum[bh * LDP + m];
    g_ctxTh[(bh * 128 + row) * LDP + m] = __float2half_rn(v);
}

// ---------------- fp16 mma core: 5-stage, issue-at-kt+3, issue-before-wait ------------
template<bool BIAS, bool DINV>
__device__ __forceinline__ void mma_core_h(const __half* __restrict__ A, int lda,
                                           const __half* __restrict__ W, int ldb,
                                           __half* __restrict__ Ch,
                                           float* __restrict__ Cf, int ldc,
                                           int K, int nvalid,
                                           const float* __restrict__ bias,
                                           float* __restrict__ maxout, int maxcols, int bhidx) {
    extern __shared__ char smc[];
    __shared__ float mred[4];
    __shared__ float Ds[128];

    const int tid = threadIdx.x;
    const int wid = tid >> 5, lid = tid & 31;
    const int wm = wid >> 1;
    const int wn = wid & 1;
    const int g = lid >> 2, q = lid & 3;

    const int la  = lid & 15;
    const int lka = (lid >> 4) << 3;
    const int lb  = (lid & 7) + ((lid >> 4) << 3);
    const int lkb = ((lid >> 3) & 1) << 3;

    const int lr = tid >> 2;
    const int lc0 = (tid & 3) << 3;

    const unsigned sbase = smem_u32(smc);
    unsigned aoff[4], boff[4];
    #pragma unroll
    for (int i = 0; i < 4; ++i) {
        aoff[i] = sbase + (unsigned)(((lr + 32 * i) * PITCHH + lc0) * 2);
        boff[i] = aoff[i] + (unsigned)HBOFFB;
    }

    const __half* Ag = A + (size_t)lr * lda + lc0;
    const __half* Wg = W + (size_t)lr * ldb + lc0;
    const size_t a32 = (size_t)32 * lda;
    const size_t w32 = (size_t)32 * ldb;

    float acc[4][8][4] = {};
    const int NT = K >> 5;

    // prologue: ktiles 0..2 -> stages 0..2 (one group each; commit unconditionally)
    #pragma unroll
    for (int p = 0; p < 3; ++p) {
        if (p < NT) {
            const unsigned d = (unsigned)(p * HSTGB);
            const int kb = p * 32;
            #pragma unroll
            for (int i = 0; i < 4; ++i) { cp16(aoff[i] + d, Ag + i * a32 + kb); cp16(boff[i] + d, Wg + i * w32 + kb); }
        }
        asm volatile("cp.async.commit_group;" ::: "memory");
    }

    int s = 0;
    for (int kt = 0; kt < NT; ++kt) {
        // issue ktile kt+3 into stage (kt+3)%5 == (kt-2)%5 (free: barrier(kt-1) passed)
        if (kt + 3 < NT) {
            int s3 = s + 3; if (s3 >= STAGES) s3 -= STAGES;
            const unsigned d = (unsigned)(s3 * HSTGB);
            const int kb = (kt + 3) * 32;
            #pragma unroll
            for (int i = 0; i < 4; ++i) { cp16(aoff[i] + d, Ag + i * a32 + kb); cp16(boff[i] + d, Wg + i * w32 + kb); }
        }
        asm volatile("cp.async.commit_group;" ::: "memory");
        asm volatile("cp.async.wait_group 3;" ::: "memory");
        __syncthreads();

        const unsigned sA = sbase + (unsigned)(s * HSTGB);
        const unsigned sB = sA + (unsigned)HBOFFB;

        #pragma unroll
        for (int ks = 0; ks < 32; ks += 16) {
            unsigned af[4][4], bf[8][2];
            #pragma unroll
            for (int mi = 0; mi < 4; ++mi) {
                const int rb = wm * 64 + mi * 16;
                unsigned addr = sA + (unsigned)((((rb + la) * PITCHH) + ks + lka) * 2);
                ldsm4(af[mi][0], af[mi][1], af[mi][2], af[mi][3], addr);
            }
            #pragma unroll
            for (int ni = 0; ni < 8; ni += 2) {
                const int cb = wn * 64 + ni * 8;
                unsigned addr = sB + (unsigned)((((cb + lb) * PITCHH) + ks + lkb) * 2);
                ldsm4(bf[ni][0], bf[ni][1], bf[ni + 1][0], bf[ni + 1][1], addr);
            }
            #pragma unroll
            for (int mi = 0; mi < 4; ++mi)
                #pragma unroll
                for (int ni = 0; ni < 8; ++ni)
                    mma_f16(acc[mi][ni], af[mi][0], af[mi][1], af[mi][2], af[mi][3],
                            bf[ni][0], bf[ni][1]);
        }
        ++s; if (s == STAGES) s = 0;
    }

    if (DINV) {
        if (wn == 1 && q == 0) {
            #pragma unroll
            for (int mi = 0; mi < 4; ++mi) {
                Ds[wm * 64 + mi * 16 + g]     = acc[mi][0][0];
                Ds[wm * 64 + mi * 16 + g + 8] = acc[mi][0][2];
            }
        }
        __syncthreads();
    }

    #pragma unroll
    for (int mi = 0; mi < 4; ++mi) {
        const int r_ = wm * 64 + mi * 16 + g;
        float sc0 = 1.f, sc1 = 1.f;
        if (DINV) { sc0 = 1.f / Ds[r_]; sc1 = 1.f / Ds[r_ + 8]; }
        #pragma unroll
        for (int ni = 0; ni < 8; ++ni) {
            const int crel = wn * 64 + ni * 8 + (q << 1);
            if (crel < nvalid) {
                float2 v0 = make_float2(acc[mi][ni][0], acc[mi][ni][1]);
                float2 v1 = make_float2(acc[mi][ni][2], acc[mi][ni][3]);
                if (BIAS) {
                    v0.x += bias[crel]; v0.y += bias[crel + 1];
                    v1.x += bias[crel]; v1.y += bias[crel + 1];
                }
                if (DINV) {
                    v0.x *= sc0; v0.y *= sc0;
                    v1.x *= sc1; v1.y *= sc1;
                }
                if (Ch) {
                    *(__half2*)&Ch[(size_t)r_ * ldc + crel]       = __floats2half2_rn(v0.x, v0.y);
                    *(__half2*)&Ch[(size_t)(r_ + 8) * ldc + crel] = __floats2half2_rn(v1.x, v1.y);
                } else {
                    *(float2*)&Cf[(size_t)r_ * ldc + crel]       = v0;
                    *(float2*)&Cf[(size_t)(r_ + 8) * ldc + crel] = v1;
                }
            }
        }
    }

    if (maxout) {
        float mx = -CUDART_INF_F;
        #pragma unroll
        for (int mi = 0; mi < 4; ++mi)
            #pragma unroll
            for (int ni = 0; ni < 8; ++ni)
                #pragma unroll
                for (int e = 0; e < 4; ++e) {
                    int crel = wn * 64 + ni * 8 + (q << 1) + (e & 1);
                    if (crel < maxcols) mx = fmaxf(mx, acc[mi][ni][e]);
                }
        #pragma unroll
        for (int o = 16; o > 0; o >>= 1)
            mx = fmaxf(mx, __shfl_xor_sync(0xffffffffu, mx, o));
        if (lid == 0) mred[wid] = mx;
        __syncthreads();
        if (tid == 0) {
            float bm = fmaxf(fmaxf(mred[0], mred[1]), fmaxf(mred[2], mred[3]));
            atomicMaxFloat(&maxout[bhidx], bm);
        }
    }
}

// ---------------- wrappers (128 threads) --------------------------------------------
__global__ void __launch_bounds__(128, 2) qk_h() {
    const int z = blockIdx.z;
    const __half* W = g_wh + (size_t)z * DIMM * DIMM;
    __half* C = (z == 0) ? g_qh : g_kh;
    const int row0 = blockIdx.y * 128, col0 = blockIdx.x * 128;
    mma_core_h<false, false>(g_xh + (size_t)row0 * DIMM, DIMM,
                    W + (size_t)col0 * DIMM, DIMM,
                    C + (size_t)row0 * DIMM + col0, nullptr, DIMM, DIMM, 128,
                    nullptr, nullptr, 0, 0);
}

__global__ void __launch_bounds__(128, 2) v_h() {
    const int row0 = blockIdx.y * 128, col0 = blockIdx.x * 128;
    mma_core_h<false, false>(g_xh + (size_t)row0 * DIMM, DIMM,
                    g_wh + 2 * (size_t)DIMM * DIMM + (size_t)col0 * DIMM, DIMM,
                    g_vh + (size_t)row0 * DIMM + col0, nullptr, DIMM, DIMM, 128,
                    nullptr, nullptr, 0, 0);
}

__global__ void __launch_bounds__(128, 2) final_h(const float* __restrict__ bo,
                                                  float* __restrict__ out) {
    const int row0 = blockIdx.y * 128, col0 = blockIdx.x * 128;
    mma_core_h<true, false>(g_attnh + (size_t)row0 * DIMM, DIMM,
                   g_wh + 3 * (size_t)DIMM * DIMM + (size_t)col0 * DIMM, DIMM,
                   nullptr, out + (size_t)row0 * DIMM + col0, DIMM, DIMM, 128,
                   bo + col0, nullptr, 0, 0);
}

__global__ void __launch_bounds__(128, 2) dash_h() {
    const int z = blockIdx.z;
    const __half* src = z ? g_kh : g_qh;
    __half* dst = z ? g_kpd : g_qpd;
    const int bh = blockIdx.y >> 5, nc = blockIdx.y & 31;
    const int b = bh >> 4, h = bh & 15;
    const int col0 = blockIdx.x * 128;
    const int row0 = nc * 128;
    mma_core_h<false, false>(src + ((size_t)(b * Nn) + row0) * DIMM + h * Dd, DIMM,
                    g_projh + (size_t)col0 * Dd, Dd,
                    dst + ((size_t)bh * Nn + row0) * LDP + col0, nullptr, LDP,
                    Dd, LDP - col0, nullptr,
                    z ? g_kmax : nullptr, Mm - col0, bh);
}

__global__ void __launch_bounds__(128, 2) out_mma_h() {
    const int t = blockIdx.y;
    const int bh = t >> 5, nt = t & 31;
    const int b = bh >> 4, h = bh & 15;
    const int row0 = nt * 128;
    mma_core_h<false, true>(g_qpd + ((size_t)bh * Nn + row0) * LDP, LDP,
                    g_ctxTh + (size_t)bh * 128 * LDP, LDP,
                    g_attnh + ((size_t)(b * Nn) + row0) * DIMM + h * Dd, nullptr, DIMM,
                    LDP, Dd, nullptr, nullptr, 0, 0);
}

// ---------------- ctx via fp16 ldmatrix.trans (5-stage, issue-at-kt+3) ------------------
#define PA 136
#define PB 72
#define CCT 5
__global__ void __launch_bounds__(256) ctx_mma_h() {
    __shared__ __half sa[CCT * 16 * PA];
    __shared__ __half sb[CCT * 16 * PB];

    const int tid = threadIdx.x;
    const int wid = tid >> 5, lid = tid & 31;
    const int wm = wid >> 1, wn = wid & 1;
    const int g = lid >> 2, q = lid & 3;
    const int bh = blockIdx.x, b = bh >> 4, h = bh & 15;
    const int m0 = blockIdx.y << 7;
    const int n0 = blockIdx.z << 9;

    const int arow = tid >> 4, ac = (tid & 15) << 3;
    const int brow = tid >> 3, bc = (tid & 7) << 3;

    const unsigned sab = smem_u32(sa);
    const unsigned sbb = smem_u32(sb);
    const unsigned aoff = sab + (unsigned)((arow * PA + ac) * 2);
    const unsigned boff = sbb + (unsigned)((brow * PB + bc) * 2);
    const unsigned stga = (unsigned)(16 * PA * 2);
    const unsigned stgb = (unsigned)(16 * PB * 2);

    const __half* Ag = g_kpd + ((size_t)bh * Nn + n0 + arow) * LDP + m0 + ac;
    const __half* Bg = g_vh + ((size_t)(b * Nn) + n0 + brow) * DIMM + h * Dd + bc;

    const int krowA = (lid & 7) + ((lid >> 4) << 3);
    const int mcolo = ((lid >> 3) & 1) << 3;
    const int krowB = (lid & 7) + (((lid >> 3) & 1) << 3);
    const int ecolo = (lid >> 4) << 3;

    float acc[2][4][4] = {};
    const int NT = 32;

    #pragma unroll
    for (int p = 0; p < 3; ++p) {
        const int kb = p * 16;
        cp16(aoff + p * stga, Ag + (size_t)kb * LDP);
        if (tid < 128) cp16(boff + p * stgb, Bg + (size_t)kb * DIMM);
        asm volatile("cp.async.commit_group;" ::: "memory");
    }

    int s = 0;
    for (int kt = 0; kt < NT; ++kt) {
        if (kt + 3 < NT) {
            int s3 = s + 3; if (s3 >= CCT) s3 -= CCT;
            const int kb = (kt + 3) * 16;
            cp16(aoff + s3 * stga, Ag + (size_t)kb * LDP);
            if (tid < 128) cp16(boff + s3 * stgb, Bg + (size_t)kb * DIMM);
        }
        asm volatile("cp.async.commit_group;" ::: "memory");
        asm volatile("cp.async.wait_group 3;" ::: "memory");
        __syncthreads();

        const unsigned sA = sab + (unsigned)(s * stga);
        const unsigned sB = sbb + (unsigned)(s * stgb);

        unsigned af[2][4], bf[4][2];
        #pragma unroll
        for (int mi = 0; mi < 2; ++mi) {
            const int rb = wm * 32 + mi * 16;
            unsigned addr = sA + (unsigned)((krowA * PA + rb + mcolo) * 2);
            ldsm4t(af[mi][0], af[mi][1], af[mi][2], af[mi][3], addr);
        }
        #pragma unroll
        for (int nj = 0; nj < 2; ++nj) {
            const int cb = wn * 32 + nj * 16;
            unsigned addr = sB + (unsigned)((krowB * PB + cb + ecolo) * 2);
            ldsm4t(bf[2*nj][0], bf[2*nj][1], bf[2*nj+1][0], bf[2*nj+1][1], addr);
        }
        #pragma unroll
        for (int mi = 0; mi < 2; ++mi)
            #pragma unroll
            for (int ni = 0; ni < 4; ++ni)
                mma_f16(acc[mi][ni], af[mi][0], af[mi][1], af[mi][2], af[mi][3],
                        bf[ni][0], bf[ni][1]);

        ++s; if (s == CCT) s = 0;
    }
    asm volatile("cp.async.wait_group 0;" ::: "memory");

    #pragma unroll
    for (int mi = 0; mi < 2; ++mi) {
        const int mA = m0 + wm * 32 + mi * 16 + g;
        #pragma unroll
        for (int ni = 0; ni < 4; ++ni) {
            const int e0 = wn * 32 + ni * 8 + (q << 1);
            if (mA < Mm) {
                atomicAdd(&g_ctxT[((size_t)bh * 128 + e0) * LDP + mA], acc[mi][ni][0]);
                atomicAdd(&g_ctxT[((size_t)bh * 128 + e0 + 1) * LDP + mA], acc[mi][ni][1]);
            }
            if (mA + 8 < Mm) {
                atomicAdd(&g_ctxT[((size_t)bh * 128 + e0) * LDP + mA + 8], acc[mi][ni][2]);
                atomicAdd(&g_ctxT[((size_t)bh * 128 + e0 + 1) * LDP + mA + 8], acc[mi][ni][3]);
            }
        }
    }
}

// ---------------- exp_q: in-place half dash -> features --------------------------------
__global__ void __launch_bounds__(256) expq_kernel() {
    const int warp = threadIdx.x >> 5, lane = threadIdx.x & 31;
    const int r = blockIdx.x * 8 + warp;
    const int bh = r >> 12, n = r & 4095;
    const int b = bh >> 4, h = bh & 15;

    const __half* qrow = g_qh + ((size_t)(b * Nn) + n) * DIMM + h * Dd;
    float q0 = __half2float(qrow[lane]), q1 = __half2float(qrow[lane + 32]);
    float s = q0 * q0 + q1 * q1;
    #pragma unroll
    for (int o = 16; o > 0; o >>= 1) s += __shfl_xor_sync(0xffffffffu, s, o);
    const float diag = 0.0625f * s;

    __half* row = g_qpd + (size_t)r * LDP;
    float d[9];
    float mx = -CUDART_INF_F;
    #pragma unroll
    for (int i = 0; i < 9; ++i) {
        int m = lane + i * 32;
        d[i] = __half2float(row[m]);
        if (m < Mm) mx = fmaxf(mx, d[i]);
    }
    #pragma unroll
    for (int o = 16; o > 0; o >>= 1) mx = fmaxf(mx, __shfl_xor_sync(0xffffffffu, mx, o));
    const float sub = diag + mx;
    #pragma unroll
    for (int i = 0; i < 9; ++i) {
        int m = lane + i * 32;
        row[m] = (m < Mm) ? __float2half_rn(RATIO * (fexp(d[i] - sub) + EPSV)) : __half(0.f);
    }
}

// ---------------- exp_k + fused k_cumsum (in-place half) -------------------------------
__global__ void __launch_bounds__(256) expk_kernel() {
    __shared__ float sums[LDP];
    const int tid = threadIdx.x;
    for (int i = tid; i < LDP; i += 256) sums[i] = 0.f;
    __syncthreads();

    const int warp = tid >> 5, lane = tid & 31;
    const int r = blockIdx.x * 8 + warp;
    const int bh = r >> 12, n = r & 4095;
    const int b = bh >> 4, h = bh & 15;

    const __half* krow = g_kh + ((size_t)(b * Nn) + n) * DIMM + h * Dd;
    float k0 = __half2float(krow[lane]), k1 = __half2float(krow[lane + 32]);
    float s = k0 * k0 + k1 * k1;
    #pragma unroll
    for (int o = 16; o > 0; o >>= 1) s += __shfl_xor_sync(0xffffffffu, s, o);
    const float sub = 0.0625f * s + g_kmax[bh];

    __half* row = g_kpd + (size_t)r * LDP;
    #pragma unroll
    for (int i = 0; i < 9; ++i) {
        int m = lane + i * 32;
        if (m < Mm) {
            __half hv = __float2half_rn(RATIO * (fexp(__half2float(row[m]) - sub) + EPSV));
            row[m] = hv;
            atomicAdd(&sums[m], __half2float(hv));
        } else {
            row[m] = __half(0.f);
        }
    }
    __syncthreads();
    for (int i = tid; i < LDP; i += 256)
        atomicAdd(&g_kcum[bh * LDP + i], sums[i]);
}

// ---------------- launcher --------------------------------------------------------------
extern "C" void kernel_launch(void* const* d_in, const int* in_sizes, int n_in,
                              void* d_out, int out_size) {
    const float* x    = (const float*)d_in[0];
    const float* Wq   = (const float*)d_in[1];
    const float* Wk   = (const float*)d_in[2];
    const float* Wv   = (const float*)d_in[3];
    const float* Wo   = (const float*)d_in[4];
    const float* bo   = (const float*)d_in[5];
    const float* proj = (const float*)d_in[6];
    float* out = (float*)d_out;

    static int init_done = 0;
    static cudaStream_t s1, s2;
    static cudaEvent_t evF, ev1, ev2, evB, evC, evQ, evV;
    if (!init_done) {
        cudaFuncSetAttribute(qk_h,      cudaFuncAttributeMaxDynamicSharedMemorySize, CORE_SMEM);
        cudaFuncSetAttribute(v_h,       cudaFuncAttributeMaxDynamicSharedMemorySize, CORE_SMEM);
        cudaFuncSetAttribute(final_h,   cudaFuncAttributeMaxDynamicSharedMemorySize, CORE_SMEM);
        cudaFuncSetAttribute(dash_h,    cudaFuncAttributeMaxDynamicSharedMemorySize, CORE_SMEM);
        cudaFuncSetAttribute(out_mma_h, cudaFuncAttributeMaxDynamicSharedMemorySize, CORE_SMEM);
        cudaStreamCreateWithFlags(&s1, cudaStreamNonBlocking);
        cudaStreamCreateWithFlags(&s2, cudaStreamNonBlocking);
        cudaEventCreateWithFlags(&evF, cudaEventDisableTiming);
        cudaEventCreateWithFlags(&ev1, cudaEventDisableTiming);
        cudaEventCreateWithFlags(&ev2, cudaEventDisableTiming);
        cudaEventCreateWithFlags(&evB, cudaEventDisableTiming);
        cudaEventCreateWithFlags(&evC, cudaEventDisableTiming);
        cudaEventCreateWithFlags(&evQ, cudaEventDisableTiming);
        cudaEventCreateWithFlags(&evV, cudaEventDisableTiming);
        init_done = 1;
    }

    cudaEventRecord(evF, 0);
    cudaStreamWaitEvent(s1, evF, 0);
    cudaStreamWaitEvent(s2, evF, 0);

    round_xh<<<ROWS * DIMM / 4 / 256, 256>>>(x);
    round_wh<<<dim3(DIMM * DIMM / 4 / 256, 4), 256, 0, s1>>>(Wq, Wk, Wv, Wo);
    prep_small<<<((unsigned)((size_t)BHh * Dd * LDP + 255) / 256), 256, 0, s2>>>(proj);

    cudaEventRecord(ev1, s1);
    cudaEventRecord(ev2, s2);
    cudaStreamWaitEvent(0, ev1, 0);
    cudaStreamWaitEvent(0, ev2, 0);

    cudaEventRecord(evB, 0);
    cudaStreamWaitEvent(s2, evB, 0);
    v_h<<<dim3(DIMM / 128, ROWS / 128), 128, CORE_SMEM, s2>>>();
    cudaEventRecord(evV, s2);

    qk_h<<<dim3(DIMM / 128, ROWS / 128, 2), 128, CORE_SMEM>>>();
    dash_h<<<dim3(3, BHh * 32, 2), 128, CORE_SMEM>>>();

    cudaEventRecord(evC, 0);
    cudaStreamWaitEvent(s1, evC, 0);
    expq_kernel<<<BHh * Nn / 8, 256, 0, s1>>>();
    cudaEventRecord(evQ, s1);

    expk_kernel<<<BHh * Nn / 8, 256>>>();
    cudaStreamWaitEvent(0, evV, 0);
    ctx_mma_h<<<dim3(BHh, 3, 8), 256>>>();
    fix_kernel<<<(unsigned)(((size_t)BHh * 65 * LDP + 255) / 256), 256>>>();

    cudaStreamWaitEvent(0, evQ, 0);
    out_mma_h<<<dim3(1, BHh * 32), 128, CORE_SMEM>>>();

    final_h<<<dim3(DIMM / 128, ROWS / 128), 128, CORE_SMEM>>>(bo, out);
}

// round 17
// speedup vs baseline: 1.2048x; 1.2048x over previous
#include <cuda_runtime.h>
#include <cuda_fp16.h>
#include <math.h>
#include <math_constants.h>

// Problem constants
#define Bz   2
#define Nn   4096
#define DIMM 1024
#define Hh   16
#define Dd   64
#define Mm   266
#define BHh  (Bz*Hh)        // 32
#define ROWS (Bz*Nn)        // 8192
#define LDP  288            // padded feature row length

#define NORMALIZER 0.35355339059327373f   // 64^-0.25
#define RATIO      0.061313933948496576f  // 266^-0.5
#define EPSV       1e-4f
#define LOG2E      1.4426950408889634f

#define STAGES  4
#define PITCHH  40
#define HSTGB   (128*PITCHH*2)                     // 10240 B per operand stage
#define HBOFFB  (STAGES*HSTGB)                     // 40960 B
#define CORE_SMEM (STAGES*HSTGB*2)                 // 81920 B

// ---------------- scratch -------------------------------------------------------
__device__ __half g_xh[ROWS*DIMM];
__device__ __half g_wh[4*(size_t)DIMM*DIMM];
__device__ __half g_projh[384*Dd];
__device__ __half g_qh[ROWS*DIMM];
__device__ __half g_kh[ROWS*DIMM];
__device__ __half g_vh[ROWS*DIMM];
__device__ __half g_attnh[ROWS*DIMM];
__device__ __half g_qpd[(size_t)BHh*Nn*LDP + 128]; // raw q dash -> features (in-place)
__device__ __half g_kpd[(size_t)BHh*Nn*LDP + 128]; // raw k dash -> features (in-place)
__device__ float  g_kmax[BHh];
__device__ float  g_kcum[BHh*LDP];
__device__ float  g_ctxT[(size_t)BHh*128*LDP];     // fp32 atomics target [e][m]
__device__ __half g_ctxTh[(size_t)BHh*128*LDP];    // row 64 = kcum; 65..127 stay 0

// ---------------- helpers -------------------------------------------------------
__device__ __forceinline__ unsigned smem_u32(const void* p) {
    unsigned a;
    asm("{ .reg .u64 t; cvta.to.shared.u64 t, %1; cvt.u32.u64 %0, t; }" : "=r"(a) : "l"(p));
    return a;
}
__device__ __forceinline__ float fexp(float x) {
    float y;
    asm("ex2.approx.f32 %0, %1;" : "=f"(y) : "f"(x * LOG2E));
    return y;
}
__device__ __forceinline__ void cp16(unsigned dst, const void* src) {
    asm volatile("cp.async.ca.shared.global [%0], [%1], 16;" :: "r"(dst), "l"(src));
}
__device__ __forceinline__ void ldsm4(unsigned& r0, unsigned& r1, unsigned& r2, unsigned& r3,
                                      unsigned addr) {
    asm volatile("ldmatrix.sync.aligned.m8n8.x4.shared.b16 {%0,%1,%2,%3}, [%4];"
        : "=r"(r0), "=r"(r1), "=r"(r2), "=r"(r3) : "r"(addr));
}
__device__ __forceinline__ void ldsm4t(unsigned& r0, unsigned& r1, unsigned& r2, unsigned& r3,
                                       unsigned addr) {
    asm volatile("ldmatrix.sync.aligned.m8n8.x4.trans.shared.b16 {%0,%1,%2,%3}, [%4];"
        : "=r"(r0), "=r"(r1), "=r"(r2), "=r"(r3) : "r"(addr));
}
__device__ __forceinline__ void mma_f16(float c[4],
                                        unsigned a0, unsigned a1, unsigned a2, unsigned a3,
                                        unsigned b0, unsigned b1) {
    asm volatile(
        "mma.sync.aligned.m16n8k16.row.col.f32.f16.f16.f32 "
        "{%0,%1,%2,%3}, {%4,%5,%6,%7}, {%8,%9}, {%0,%1,%2,%3};"
        : "+f"(c[0]), "+f"(c[1]), "+f"(c[2]), "+f"(c[3])
        : "r"(a0), "r"(a1), "r"(a2), "r"(a3), "r"(b0), "r"(b1));
}
__device__ __forceinline__ void atomicMaxFloat(float* addr, float val) {
    int* a = (int*)addr;
    int old = *a;
    while (__int_as_float(old) < val) {
        int assumed = old;
        old = atomicCAS(a, assumed, __float_as_int(val));
        if (old == assumed) break;
    }
}

// ---------------- prep / conversion passes -----------------------------------------
__global__ void prep_small(const float* __restrict__ proj) {
    size_t t = (size_t)blockIdx.x * blockDim.x + threadIdx.x;
    if (t < BHh) g_kmax[t] = -CUDART_INF_F;
    if (t < BHh * LDP) g_kcum[t] = 0.f;
    if (t < 384 * Dd) {
        int m = (int)(t >> 6);
        g_projh[t] = (m < Mm) ? __float2half_rn(proj[t] * NORMALIZER) : __half(0.f);
    }
    if (t < (size_t)BHh * Dd * LDP) {
        size_t bh = t / (Dd * LDP);
        size_t rem = t - bh * (Dd * LDP);
        g_ctxT[bh * 128 * LDP + rem] = 0.f;
    }
}
__global__ void round_xh(const float* __restrict__ in) {
    int i = blockIdx.x * blockDim.x + threadIdx.x;
    float4 v = ((const float4*)in)[i];
    ((__half2*)g_xh)[2*i]   = __floats2half2_rn(v.x, v.y);
    ((__half2*)g_xh)[2*i+1] = __floats2half2_rn(v.z, v.w);
}
__global__ void round_wh(const float* __restrict__ w0, const float* __restrict__ w1,
                         const float* __restrict__ w2, const float* __restrict__ w3) {
    int z = blockIdx.y;
    const float* w = (z == 0) ? w0 : (z == 1) ? w1 : (z == 2) ? w2 : w3;
    int i = blockIdx.x * blockDim.x + threadIdx.x;
    float4 v = ((const float4*)w)[i];
    __half2* o = (__half2*)(g_wh + (size_t)z * DIMM * DIMM);
    o[2*i]   = __floats2half2_rn(v.x, v.y);
    o[2*i+1] = __floats2half2_rn(v.z, v.w);
}
__global__ void fix_kernel() {
    size_t t = (size_t)blockIdx.x * 256 + threadIdx.x;
    const size_t per_bh = (size_t)65 * LDP;
    if (t >= (size_t)BHh * per_bh) return;
    size_t bh = t / per_bh;
    size_t rem = t - bh * per_bh;
    int row = (int)(rem / LDP), m = (int)(rem - (size_t)row * LDP);
    float v = (row < 64) ? g_ctxT[(bh * 128 + row) * LDP + m] : g_kcum[bh * LDP + m];
    g_ctxTh[(bh * 128 + row) * LDP + m] = __float2half_rn(v);
}

// ---------------- fp16 mma core (round-15 proven: 4-stage, issue-at-kt+2) -------------
template<bool BIAS, bool DINV>
__device__ __forceinline__ void mma_core_h(const __half* __restrict__ A, int lda,
                                           const __half* __restrict__ W, int ldb,
                                           __half* __restrict__ Ch,
                                           float* __restrict__ Cf, int ldc,
                                           int K, int nvalid,
                                           const float* __restrict__ bias,
                                           float* __restrict__ maxout, int maxcols, int bhidx) {
    extern __shared__ char smc[];
    __shared__ float mred[4];
    __shared__ float Ds[128];

    const int tid = threadIdx.x;
    const int wid = tid >> 5, lid = tid & 31;
    const int wm = wid >> 1;
    const int wn = wid & 1;
    const int g = lid >> 2, q = lid & 3;

    const int la  = lid & 15;
    const int lka = (lid >> 4) << 3;
    const int lb  = (lid & 7) + ((lid >> 4) << 3);
    const int lkb = ((lid >> 3) & 1) << 3;

    const int lr = tid >> 2;
    const int lc0 = (tid & 3) << 3;

    const unsigned sbase = smem_u32(smc);
    unsigned aoff[4], boff[4];
    #pragma unroll
    for (int i = 0; i < 4; ++i) {
        aoff[i] = sbase + (unsigned)(((lr + 32 * i) * PITCHH + lc0) * 2);
        boff[i] = aoff[i] + (unsigned)HBOFFB;
    }

    const __half* Ag = A + (size_t)lr * lda + lc0;
    const __half* Wg = W + (size_t)lr * ldb + lc0;
    const size_t a32 = (size_t)32 * lda;
    const size_t w32 = (size_t)32 * ldb;

    float acc[4][8][4] = {};
    const int NT = K >> 5;

    {
        #pragma unroll
        for (int i = 0; i < 4; ++i) { cp16(aoff[i], Ag + i * a32); cp16(boff[i], Wg + i * w32); }
        asm volatile("cp.async.commit_group;" ::: "memory");
        if (NT > 1) {
            #pragma unroll
            for (int i = 0; i < 4; ++i) { cp16(aoff[i] + HSTGB, Ag + i * a32 + 32); cp16(boff[i] + HSTGB, Wg + i * w32 + 32); }
        }
        asm volatile("cp.async.commit_group;" ::: "memory");
    }

    int s = 0;
    for (int kt = 0; kt < NT; ++kt) {
        if (kt + 2 < NT) {
            int s2 = s + 2; if (s2 >= STAGES) s2 -= STAGES;
            const unsigned d = (unsigned)(s2 * HSTGB);
            const int kb = (kt + 2) * 32;
            #pragma unroll
            for (int i = 0; i < 4; ++i) { cp16(aoff[i] + d, Ag + i * a32 + kb); cp16(boff[i] + d, Wg + i * w32 + kb); }
        }
        asm volatile("cp.async.commit_group;" ::: "memory");
        asm volatile("cp.async.wait_group 2;" ::: "memory");
        __syncthreads();

        const unsigned sA = sbase + (unsigned)(s * HSTGB);
        const unsigned sB = sA + (unsigned)HBOFFB;

        #pragma unroll
        for (int ks = 0; ks < 32; ks += 16) {
            unsigned af[4][4], bf[8][2];
            #pragma unroll
            for (int mi = 0; mi < 4; ++mi) {
                const int rb = wm * 64 + mi * 16;
                unsigned addr = sA + (unsigned)((((rb + la) * PITCHH) + ks + lka) * 2);
                ldsm4(af[mi][0], af[mi][1], af[mi][2], af[mi][3], addr);
            }
            #pragma unroll
            for (int ni = 0; ni < 8; ni += 2) {
                const int cb = wn * 64 + ni * 8;
                unsigned addr = sB + (unsigned)((((cb + lb) * PITCHH) + ks + lkb) * 2);
                ldsm4(bf[ni][0], bf[ni][1], bf[ni + 1][0], bf[ni + 1][1], addr);
            }
            #pragma unroll
            for (int mi = 0; mi < 4; ++mi)
                #pragma unroll
                for (int ni = 0; ni < 8; ++ni)
                    mma_f16(acc[mi][ni], af[mi][0], af[mi][1], af[mi][2], af[mi][3],
                            bf[ni][0], bf[ni][1]);
        }
        ++s; if (s == STAGES) s = 0;
    }

    if (DINV) {
        if (wn == 1 && q == 0) {
            #pragma unroll
            for (int mi = 0; mi < 4; ++mi) {
                Ds[wm * 64 + mi * 16 + g]     = acc[mi][0][0];
                Ds[wm * 64 + mi * 16 + g + 8] = acc[mi][0][2];
            }
        }
        __syncthreads();
    }

    #pragma unroll
    for (int mi = 0; mi < 4; ++mi) {
        const int r_ = wm * 64 + mi * 16 + g;
        float sc0 = 1.f, sc1 = 1.f;
        if (DINV) { sc0 = 1.f / Ds[r_]; sc1 = 1.f / Ds[r_ + 8]; }
        #pragma unroll
        for (int ni = 0; ni < 8; ++ni) {
            const int crel = wn * 64 + ni * 8 + (q << 1);
            if (crel < nvalid) {
                float2 v0 = make_float2(acc[mi][ni][0], acc[mi][ni][1]);
                float2 v1 = make_float2(acc[mi][ni][2], acc[mi][ni][3]);
                if (BIAS) {
                    v0.x += bias[crel]; v0.y += bias[crel + 1];
                    v1.x += bias[crel]; v1.y += bias[crel + 1];
                }
                if (DINV) {
                    v0.x *= sc0; v0.y *= sc0;
                    v1.x *= sc1; v1.y *= sc1;
                }
                if (Ch) {
                    *(__half2*)&Ch[(size_t)r_ * ldc + crel]       = __floats2half2_rn(v0.x, v0.y);
                    *(__half2*)&Ch[(size_t)(r_ + 8) * ldc + crel] = __floats2half2_rn(v1.x, v1.y);
                } else {
                    *(float2*)&Cf[(size_t)r_ * ldc + crel]       = v0;
                    *(float2*)&Cf[(size_t)(r_ + 8) * ldc + crel] = v1;
                }
            }
        }
    }

    if (maxout) {
        float mx = -CUDART_INF_F;
        #pragma unroll
        for (int mi = 0; mi < 4; ++mi)
            #pragma unroll
            for (int ni = 0; ni < 8; ++ni)
                #pragma unroll
                for (int e = 0; e < 4; ++e) {
                    int crel = wn * 64 + ni * 8 + (q << 1) + (e & 1);
                    if (crel < maxcols) mx = fmaxf(mx, acc[mi][ni][e]);
                }
        #pragma unroll
        for (int o = 16; o > 0; o >>= 1)
            mx = fmaxf(mx, __shfl_xor_sync(0xffffffffu, mx, o));
        if (lid == 0) mred[wid] = mx;
        __syncthreads();
        if (tid == 0) {
            float bm = fmaxf(fmaxf(mred[0], mred[1]), fmaxf(mred[2], mred[3]));
            atomicMaxFloat(&maxout[bhidx], bm);
        }
    }
}

// ---------------- wrappers (128 threads) --------------------------------------------
__global__ void __launch_bounds__(128, 2) qk_h() {
    const int z = blockIdx.z;
    const __half* W = g_wh + (size_t)z * DIMM * DIMM;
    __half* C = (z == 0) ? g_qh : g_kh;
    const int row0 = blockIdx.y * 128, col0 = blockIdx.x * 128;
    mma_core_h<false, false>(g_xh + (size_t)row0 * DIMM, DIMM,
                    W + (size_t)col0 * DIMM, DIMM,
                    C + (size_t)row0 * DIMM + col0, nullptr, DIMM, DIMM, 128,
                    nullptr, nullptr, 0, 0);
}

__global__ void __launch_bounds__(128, 2) v_h() {
    const int row0 = blockIdx.y * 128, col0 = blockIdx.x * 128;
    mma_core_h<false, false>(g_xh + (size_t)row0 * DIMM, DIMM,
                    g_wh + 2 * (size_t)DIMM * DIMM + (size_t)col0 * DIMM, DIMM,
                    g_vh + (size_t)row0 * DIMM + col0, nullptr, DIMM, DIMM, 128,
                    nullptr, nullptr, 0, 0);
}

__global__ void __launch_bounds__(128, 2) final_h(const float* __restrict__ bo,
                                                  float* __restrict__ out) {
    const int row0 = blockIdx.y * 128, col0 = blockIdx.x * 128;
    mma_core_h<true, false>(g_attnh + (size_t)row0 * DIMM, DIMM,
                   g_wh + 3 * (size_t)DIMM * DIMM + (size_t)col0 * DIMM, DIMM,
                   nullptr, out + (size_t)row0 * DIMM + col0, DIMM, DIMM, 128,
                   bo + col0, nullptr, 0, 0);
}

__global__ void __launch_bounds__(128, 2) dash_h() {
    const int z = blockIdx.z;
    const __half* src = z ? g_kh : g_qh;
    __half* dst = z ? g_kpd : g_qpd;
    const int bh = blockIdx.y >> 5, nc = blockIdx.y & 31;
    const int b = bh >> 4, h = bh & 15;
    const int col0 = blockIdx.x * 128;
    const int row0 = nc * 128;
    mma_core_h<false, false>(src + ((size_t)(b * Nn) + row0) * DIMM + h * Dd, DIMM,
                    g_projh + (size_t)col0 * Dd, Dd,
                    dst + ((size_t)bh * Nn + row0) * LDP + col0, nullptr, LDP,
                    Dd, LDP - col0, nullptr,
                    z ? g_kmax : nullptr, Mm - col0, bh);
}

__global__ void __launch_bounds__(128, 2) out_mma_h() {
    const int t = blockIdx.y;
    const int bh = t >> 5, nt = t & 31;
    const int b = bh >> 4, h = bh & 15;
    const int row0 = nt * 128;
    mma_core_h<false, true>(g_qpd + ((size_t)bh * Nn + row0) * LDP, LDP,
                    g_ctxTh + (size_t)bh * 128 * LDP, LDP,
                    g_attnh + ((size_t)(b * Nn) + row0) * DIMM + h * Dd, nullptr, DIMM,
                    LDP, Dd, nullptr, nullptr, 0, 0);
}

// ---------------- ctx via fp16 ldmatrix.trans (round-15 proven: 4-stage) ----------------
#define PA 136
#define PB 72
#define CCT 4
__global__ void __launch_bounds__(256) ctx_mma_h() {
    __shared__ __half sa[CCT * 16 * PA];
    __shared__ __half sb[CCT * 16 * PB];

    const int tid = threadIdx.x;
    const int wid = tid >> 5, lid = tid & 31;
    const int wm = wid >> 1, wn = wid & 1;
    const int g = lid >> 2, q = lid & 3;
    const int bh = blockIdx.x, b = bh >> 4, h = bh & 15;
    const int m0 = blockIdx.y << 7;
    const int n0 = blockIdx.z << 9;

    const int arow = tid >> 4, ac = (tid & 15) << 3;
    const int brow = tid >> 3, bc = (tid & 7) << 3;

    const unsigned sab = smem_u32(sa);
    const unsigned sbb = smem_u32(sb);
    const unsigned aoff = sab + (unsigned)((arow * PA + ac) * 2);
    const unsigned boff = sbb + (unsigned)((brow * PB + bc) * 2);
    const unsigned stga = (unsigned)(16 * PA * 2);
    const unsigned stgb = (unsigned)(16 * PB * 2);

    const __half* Ag = g_kpd + ((size_t)bh * Nn + n0 + arow) * LDP + m0 + ac;
    const __half* Bg = g_vh + ((size_t)(b * Nn) + n0 + brow) * DIMM + h * Dd + bc;

    const int krowA = (lid & 7) + ((lid >> 4) << 3);
    const int mcolo = ((lid >> 3) & 1) << 3;
    const int krowB = (lid & 7) + (((lid >> 3) & 1) << 3);
    const int ecolo = (lid >> 4) << 3;

    float acc[2][4][4] = {};
    const int NT = 32;

    {
        cp16(aoff, Ag);
        if (tid < 128) cp16(boff, Bg);
        asm volatile("cp.async.commit_group;" ::: "memory");
        cp16(aoff + stga, Ag + 16 * LDP);
        if (tid < 128) cp16(boff + stgb, Bg + 16 * DIMM);
        asm volatile("cp.async.commit_group;" ::: "memory");
    }

    int s = 0;
    for (int kt = 0; kt < NT; ++kt) {
        if (kt + 2 < NT) {
            int s2 = s + 2; if (s2 >= CCT) s2 -= CCT;
            const int kb = (kt + 2) * 16;
            cp16(aoff + s2 * stga, Ag + (size_t)kb * LDP);
            if (tid < 128) cp16(boff + s2 * stgb, Bg + (size_t)kb * DIMM);
        }
        asm volatile("cp.async.commit_group;" ::: "memory");
        asm volatile("cp.async.wait_group 2;" ::: "memory");
        __syncthreads();

        const unsigned sA = sab + (unsigned)(s * stga);
        const unsigned sB = sbb + (unsigned)(s * stgb);

        unsigned af[2][4], bf[4][2];
        #pragma unroll
        for (int mi = 0; mi < 2; ++mi) {
            const int rb = wm * 32 + mi * 16;
            unsigned addr = sA + (unsigned)((krowA * PA + rb + mcolo) * 2);
            ldsm4t(af[mi][0], af[mi][1], af[mi][2], af[mi][3], addr);
        }
        #pragma unroll
        for (int nj = 0; nj < 2; ++nj) {
            const int cb = wn * 32 + nj * 16;
            unsigned addr = sB + (unsigned)((krowB * PB + cb + ecolo) * 2);
            ldsm4t(bf[2*nj][0], bf[2*nj][1], bf[2*nj+1][0], bf[2*nj+1][1], addr);
        }
        #pragma unroll
        for (int mi = 0; mi < 2; ++mi)
            #pragma unroll
            for (int ni = 0; ni < 4; ++ni)
                mma_f16(acc[mi][ni], af[mi][0], af[mi][1], af[mi][2], af[mi][3],
                        bf[ni][0], bf[ni][1]);

        ++s; if (s == CCT) s = 0;
    }
    asm volatile("cp.async.wait_group 0;" ::: "memory");

    #pragma unroll
    for (int mi = 0; mi < 2; ++mi) {
        const int mA = m0 + wm * 32 + mi * 16 + g;
        #pragma unroll
        for (int ni = 0; ni < 4; ++ni) {
            const int e0 = wn * 32 + ni * 8 + (q << 1);
            if (mA < Mm) {
                atomicAdd(&g_ctxT[((size_t)bh * 128 + e0) * LDP + mA], acc[mi][ni][0]);
                atomicAdd(&g_ctxT[((size_t)bh * 128 + e0 + 1) * LDP + mA], acc[mi][ni][1]);
            }
            if (mA + 8 < Mm) {
                atomicAdd(&g_ctxT[((size_t)bh * 128 + e0) * LDP + mA + 8], acc[mi][ni][2]);
                atomicAdd(&g_ctxT[((size_t)bh * 128 + e0 + 1) * LDP + mA + 8], acc[mi][ni][3]);
            }
        }
    }
}

// ---------------- exp_q: half2-vectorized, in-place --------------------------------------
__global__ void __launch_bounds__(256) expq_kernel() {
    const int warp = threadIdx.x >> 5, lane = threadIdx.x & 31;
    const int r = blockIdx.x * 8 + warp;
    const int bh = r >> 12, n = r & 4095;
    const int b = bh >> 4, h = bh & 15;

    const __half* qrow = g_qh + ((size_t)(b * Nn) + n) * DIMM + h * Dd;
    float q0 = __half2float(qrow[lane]), q1 = __half2float(qrow[lane + 32]);
    float s = q0 * q0 + q1 * q1;
    #pragma unroll
    for (int o = 16; o > 0; o >>= 1) s += __shfl_xor_sync(0xffffffffu, s, o);
    const float diag = 0.0625f * s;

    __half2* row2 = (__half2*)(g_qpd + (size_t)r * LDP);
    float2 d[5];
    float mx = -CUDART_INF_F;
    #pragma unroll
    for (int i = 0; i < 5; ++i) {
        int idx = lane + i * 32;              // 0..159; valid data idx<133
        if (idx < 144) {
            d[i] = __half22float2(row2[idx]);
            if (idx < 133) mx = fmaxf(mx, fmaxf(d[i].x, d[i].y));
        }
    }
    #pragma unroll
    for (int o = 16; o > 0; o >>= 1) mx = fmaxf(mx, __shfl_xor_sync(0xffffffffu, mx, o));
    const float sub = diag + mx;
    #pragma unroll
    for (int i = 0; i < 5; ++i) {
        int idx = lane + i * 32;
        if (idx < 133) {
            row2[idx] = __floats2half2_rn(RATIO * (fexp(d[i].x - sub) + EPSV),
                                          RATIO * (fexp(d[i].y - sub) + EPSV));
        } else if (idx < 144) {
            row2[idx] = __floats2half2_rn(0.f, 0.f);
        }
    }
}

// ---------------- exp_k + fused k_cumsum (half2-vectorized) -------------------------------
__global__ void __launch_bounds__(256) expk_kernel() {
    __shared__ float sums[LDP];
    const int tid = threadIdx.x;
    for (int i = tid; i < LDP; i += 256) sums[i] = 0.f;
    __syncthreads();

    const int warp = tid >> 5, lane = tid & 31;
    const int r = blockIdx.x * 8 + warp;
    const int bh = r >> 12, n = r & 4095;
    const int b = bh >> 4, h = bh & 15;

    const __half* krow = g_kh + ((size_t)(b * Nn) + n) * DIMM + h * Dd;
    float k0 = __half2float(krow[lane]), k1 = __half2float(krow[lane + 32]);
    float s = k0 * k0 + k1 * k1;
    #pragma unroll
    for (int o = 16; o > 0; o >>= 1) s += __shfl_xor_sync(0xffffffffu, s, o);
    const float sub = 0.0625f * s + g_kmax[bh];

    __half2* row2 = (__half2*)(g_kpd + (size_t)r * LDP);
    #pragma unroll
    for (int i = 0; i < 5; ++i) {
        int idx = lane + i * 32;
        if (idx < 133) {
            float2 dv = __half22float2(row2[idx]);
            __half2 hv = __floats2half2_rn(RATIO * (fexp(dv.x - sub) + EPSV),
                                           RATIO * (fexp(dv.y - sub) + EPSV));
            row2[idx] = hv;
            float2 fv = __half22float2(hv);
            atomicAdd(&sums[2 * idx], fv.x);
            atomicAdd(&sums[2 * idx + 1], fv.y);
        } else if (idx < 144) {
            row2[idx] = __floats2half2_rn(0.f, 0.f);
        }
    }
    __syncthreads();
    for (int i = tid; i < LDP; i += 256)
        atomicAdd(&g_kcum[bh * LDP + i], sums[i]);
}

// ---------------- launcher --------------------------------------------------------------
extern "C" void kernel_launch(void* const* d_in, const int* in_sizes, int n_in,
                              void* d_out, int out_size) {
    const float* x    = (const float*)d_in[0];
    const float* Wq   = (const float*)d_in[1];
    const float* Wk   = (const float*)d_in[2];
    const float* Wv   = (const float*)d_in[3];
    const float* Wo   = (const float*)d_in[4];
    const float* bo   = (const float*)d_in[5];
    const float* proj = (const float*)d_in[6];
    float* out = (float*)d_out;

    static int init_done = 0;
    static cudaStream_t s1, s2;
    static cudaEvent_t evF, ev1, ev2, evB, evC, evQ, evV;
    if (!init_done) {
        cudaFuncSetAttribute(qk_h,      cudaFuncAttributeMaxDynamicSharedMemorySize, CORE_SMEM);
        cudaFuncSetAttribute(v_h,       cudaFuncAttributeMaxDynamicSharedMemorySize, CORE_SMEM);
        cudaFuncSetAttribute(final_h,   cudaFuncAttributeMaxDynamicSharedMemorySize, CORE_SMEM);
        cudaFuncSetAttribute(dash_h,    cudaFuncAttributeMaxDynamicSharedMemorySize, CORE_SMEM);
        cudaFuncSetAttribute(out_mma_h, cudaFuncAttributeMaxDynamicSharedMemorySize, CORE_SMEM);
        cudaStreamCreateWithFlags(&s1, cudaStreamNonBlocking);
        cudaStreamCreateWithFlags(&s2, cudaStreamNonBlocking);
        cudaEventCreateWithFlags(&evF, cudaEventDisableTiming);
        cudaEventCreateWithFlags(&ev1, cudaEventDisableTiming);
        cudaEventCreateWithFlags(&ev2, cudaEventDisableTiming);
        cudaEventCreateWithFlags(&evB, cudaEventDisableTiming);
        cudaEventCreateWithFlags(&evC, cudaEventDisableTiming);
        cudaEventCreateWithFlags(&evQ, cudaEventDisableTiming);
        cudaEventCreateWithFlags(&evV, cudaEventDisableTiming);
        init_done = 1;
    }

    cudaEventRecord(evF, 0);
    cudaStreamWaitEvent(s1, evF, 0);
    cudaStreamWaitEvent(s2, evF, 0);

    round_xh<<<ROWS * DIMM / 4 / 256, 256>>>(x);
    round_wh<<<dim3(DIMM * DIMM / 4 / 256, 4), 256, 0, s1>>>(Wq, Wk, Wv, Wo);
    prep_small<<<((unsigned)((size_t)BHh * Dd * LDP + 255) / 256), 256, 0, s2>>>(proj);

    cudaEventRecord(ev1, s1);
    cudaEventRecord(ev2, s2);
    cudaStreamWaitEvent(0, ev1, 0);
    cudaStreamWaitEvent(0, ev2, 0);

    cudaEventRecord(evB, 0);
    cudaStreamWaitEvent(s2, evB, 0);
    v_h<<<dim3(DIMM / 128, ROWS / 128), 128, CORE_SMEM, s2>>>();
    cudaEventRecord(evV, s2);

    qk_h<<<dim3(DIMM / 128, ROWS / 128, 2), 128, CORE_SMEM>>>();
    dash_h<<<dim3(3, BHh * 32, 2), 128, CORE_SMEM>>>();

    cudaEventRecord(evC, 0);
    cudaStreamWaitEvent(s1, evC, 0);
    expq_kernel<<<BHh * Nn / 8, 256, 0, s1>>>();
    cudaEventRecord(evQ, s1);

    expk_kernel<<<BHh * Nn / 8, 256>>>();
    cudaStreamWaitEvent(0, evV, 0);
    ctx_mma_h<<<dim3(BHh, 3, 8), 256>>>();
    fix_kernel<<<(unsigned)(((size_t)BHh * 65 * LDP + 255) / 256), 256>>>();

    cudaStreamWaitEvent(0, evQ, 0);
    out_mma_h<<<dim3(1, BHh * 32), 128, CORE_SMEM>>>();

    final_h<<<dim3(DIMM / 128, ROWS / 128), 128, CORE_SMEM>>>(bo, out);
}